// round 1
// baseline (speedup 1.0000x reference)
#include <cuda_runtime.h>
#include <math.h>

#define BB 4
#define CC 64
#define NN 4096
#define HHD 64
#define AHD 256
#define KK 16
#define RS 20   // padded row stride for k-dim smem arrays (16 -> 20 floats, keeps 16B alignment, kills bank conflicts)

// ---------------- scratch (no allocations allowed) ----------------
__device__ float g_val_t[BB * NN * CC];   // y1 (value), layout (B,N,C)
__device__ float g_key_t[BB * NN * CC];   // key, layout (B,N,C)
__device__ float g_agg[BB * NN * CC];     // aggregated features, layout (B,N,C)
__device__ int   g_idx[BB * NN * KK];     // knn indices

__device__ __forceinline__ void fma4(float4& a, float w, const float4 v) {
    a.x = fmaf(w, v.x, a.x);
    a.y = fmaf(w, v.y, a.y);
    a.z = fmaf(w, v.z, a.z);
    a.w = fmaf(w, v.w, a.w);
}

// ================= Kernel 1: y1 = W_start@y+b ; key = W_key@y1+b (both written transposed (B,N,C)) =================
__global__ __launch_bounds__(256) void k_linear_start_key(
    const float* __restrict__ y,
    const float* __restrict__ Ws_g, const float* __restrict__ bs_g,
    const float* __restrict__ Wk_g, const float* __restrict__ bk_g)
{
    __shared__ float ys[64][64];
    __shared__ float y1s[64][64];
    __shared__ float Ws[64][64];
    int b = blockIdx.y, n0 = blockIdx.x * 64, t = threadIdx.x;

#pragma unroll
    for (int i = 0; i < 16; i++) { int e = t + i * 256; Ws[e >> 6][e & 63] = Ws_g[e]; }
#pragma unroll
    for (int i = 0; i < 16; i++) {
        int e = t + i * 256; int c = e >> 6, p = e & 63;
        ys[c][p] = y[((size_t)b * CC + c) * NN + n0 + p];
    }
    __syncthreads();

    int p = t & 63, og = t >> 6;
    float acc[16];
#pragma unroll
    for (int i = 0; i < 16; i++) acc[i] = bs_g[og * 16 + i];
#pragma unroll 4
    for (int c = 0; c < 64; c++) {
        float yv = ys[c][p];
#pragma unroll
        for (int i = 0; i < 16; i++) acc[i] = fmaf(Ws[og * 16 + i][c], yv, acc[i]);
    }
#pragma unroll
    for (int i = 0; i < 16; i++) y1s[og * 16 + i][p] = acc[i];
    {
        float4* vo = (float4*)&g_val_t[(((size_t)b * NN) + n0 + p) * CC + og * 16];
        vo[0] = make_float4(acc[0], acc[1], acc[2], acc[3]);
        vo[1] = make_float4(acc[4], acc[5], acc[6], acc[7]);
        vo[2] = make_float4(acc[8], acc[9], acc[10], acc[11]);
        vo[3] = make_float4(acc[12], acc[13], acc[14], acc[15]);
    }
    __syncthreads();
#pragma unroll
    for (int i = 0; i < 16; i++) { int e = t + i * 256; Ws[e >> 6][e & 63] = Wk_g[e]; }
    __syncthreads();
#pragma unroll
    for (int i = 0; i < 16; i++) acc[i] = bk_g[og * 16 + i];
#pragma unroll 4
    for (int c = 0; c < 64; c++) {
        float yv = y1s[c][p];
#pragma unroll
        for (int i = 0; i < 16; i++) acc[i] = fmaf(Ws[og * 16 + i][c], yv, acc[i]);
    }
    {
        float4* ko = (float4*)&g_key_t[(((size_t)b * NN) + n0 + p) * CC + og * 16];
        ko[0] = make_float4(acc[0], acc[1], acc[2], acc[3]);
        ko[1] = make_float4(acc[4], acc[5], acc[6], acc[7]);
        ko[2] = make_float4(acc[8], acc[9], acc[10], acc[11]);
        ko[3] = make_float4(acc[12], acc[13], acc[14], acc[15]);
    }
}

// ================= Kernel 2: KNN (top-16 nearest incl. self) =================
__global__ __launch_bounds__(128) void k_knn(const float* __restrict__ x)
{
    __shared__ float sxs[128], sys[128], szs[128], ssq[128];
    int b = blockIdx.y;
    int i = blockIdx.x * 128 + threadIdx.x;
    const float* xb = x + (size_t)b * 3 * NN;
    float qx = xb[i], qy = xb[NN + i], qz = xb[2 * NN + i];
    float qsq = qx * qx + qy * qy + qz * qz;

    float bd[16]; int bi[16];
#pragma unroll
    for (int s = 0; s < 16; s++) { bd[s] = 3.0e38f; bi[s] = 0; }

    for (int c0 = 0; c0 < NN; c0 += 128) {
        int j = c0 + threadIdx.x;
        float a0 = xb[j], a1 = xb[NN + j], a2 = xb[2 * NN + j];
        sxs[threadIdx.x] = a0; sys[threadIdx.x] = a1; szs[threadIdx.x] = a2;
        ssq[threadIdx.x] = a0 * a0 + a1 * a1 + a2 * a2;
        __syncthreads();
#pragma unroll 4
        for (int jj = 0; jj < 128; jj++) {
            float dot = qx * sxs[jj] + qy * sys[jj] + qz * szs[jj];
            float d = qsq - 2.0f * dot + ssq[jj];
            if (d < bd[15]) {
                bd[15] = d; bi[15] = c0 + jj;
#pragma unroll
                for (int s = 15; s > 0; --s) {
                    if (bd[s] < bd[s - 1]) {
                        float td = bd[s]; bd[s] = bd[s - 1]; bd[s - 1] = td;
                        int ti = bi[s]; bi[s] = bi[s - 1]; bi[s - 1] = ti;
                    } else break;
                }
            }
        }
        __syncthreads();
    }
#pragma unroll
    for (int s = 0; s < 16; s++) g_idx[((size_t)b * NN + i) * KK + s] = bi[s];
}

// ================= Kernel 3: fused pe + attention MLP + softmax + aggregation =================
struct __align__(16) S3 {
    float A1s[64][257];     // [c][a], BN-folded A1 (pad 257: conflict-free transpose fill + read)
    float A2s[256][65];     // [h][c]
    float P2s[64][65];      // [h][c]
    float P1p[64][3];       // BN-folded P1
    float Wq[64][3];
    float b1p[256];         // folded bias after A1+bn2
    float s2s[256];
    float pb1p[64];         // folded bias after P1+bn1
    float s1s[64];
    float pb2s[64];
    float ab2s[64];
    float bqs[64];
    float posr[2][3][16];
    float qy[2][64];
    float vals[2][64];
    float kgu[2][64][RS];   // gathered key, then u = (q-key)+pe in place
    float th[2][64][RS];    // pe hidden, then attn logits
    float pes[2][64][RS];
    float h1s[2][256][RS];
    int   idxs[2][16];
};

__global__ void __launch_bounds__(256, 1) k_attn(
    const float* __restrict__ x,
    const float* __restrict__ Wq_g, const float* __restrict__ bq_g,
    const float* __restrict__ P1, const float* __restrict__ pb1,
    const float* __restrict__ bn1_g, const float* __restrict__ bn1_b,
    const float* __restrict__ bn1_m, const float* __restrict__ bn1_v,
    const float* __restrict__ P2, const float* __restrict__ pb2,
    const float* __restrict__ A1, const float* __restrict__ ab1,
    const float* __restrict__ bn2_g, const float* __restrict__ bn2_b,
    const float* __restrict__ bn2_m, const float* __restrict__ bn2_v,
    const float* __restrict__ A2, const float* __restrict__ ab2)
{
    extern __shared__ char smraw[];
    S3& s = *(S3*)smraw;
    int t = threadIdx.x;
    int b = blockIdx.x >> 9;               // 512 tiles of 8 points per batch
    int n_base = (blockIdx.x & 511) * 8;

    // ---- fold BN into weights/biases, stage weights to smem ----
    {
        float s2 = bn2_g[t] / sqrtf(bn2_v[t] + 1e-5f);
        s.s2s[t] = s2;
        s.b1p[t] = (ab1[t] - bn2_m[t]) * s2 + bn2_b[t];
    }
    if (t < 64) {
        float s1 = bn1_g[t] / sqrtf(bn1_v[t] + 1e-5f);
        s.s1s[t] = s1;
        s.pb1p[t] = (pb1[t] - bn1_m[t]) * s1 + bn1_b[t];
        s.pb2s[t] = pb2[t];
        s.ab2s[t] = ab2[t];
        s.bqs[t] = bq_g[t];
    }
    if (t < 192) s.Wq[t / 3][t % 3] = Wq_g[t];
    __syncthreads();
    if (t < 192) s.P1p[t / 3][t % 3] = P1[t] * s.s1s[t / 3];
#pragma unroll
    for (int i = 0; i < 64; i++) { int e = t + i * 256; int a = e >> 6, c = e & 63; s.A1s[c][a] = A1[e] * s.s2s[a]; }
#pragma unroll
    for (int i = 0; i < 64; i++) { int e = t + i * 256; int c = e >> 8, h = e & 255; s.A2s[h][c] = A2[e]; }
#pragma unroll
    for (int i = 0; i < 16; i++) { int e = t + i * 256; int c = e >> 6, h = e & 63; s.P2s[h][c] = P2[e]; }
    __syncthreads();

    const float* xb = x + (size_t)b * 3 * NN;

    for (int pp = 0; pp < 8; pp += 2) {
        int n0 = n_base + pp;

        if (t < 32) {
            int pt = t >> 4, k = t & 15;
            s.idxs[pt][k] = g_idx[((size_t)b * NN + n0 + pt) * KK + k];
        }
        __syncthreads();

        // ---- stage 0: gathers / small linears ----
        if (t < 96) {
            int pt = t / 48, r = t % 48, d = r >> 4, k = r & 15;
            int j = s.idxs[pt][k];
            s.posr[pt][d][k] = xb[d * NN + n0 + pt] - xb[d * NN + j];
        } else if (t >= 128) {
            int tt = t - 128, pt = tt >> 6, c = tt & 63;
            int n = n0 + pt;
            s.qy[pt][c] = s.bqs[c] + s.Wq[c][0] * xb[n] + s.Wq[c][1] * xb[NN + n] + s.Wq[c][2] * xb[2 * NN + n];
        }
        if (t < 128) {
            int pt = t >> 6, c = t & 63;
            s.vals[pt][c] = g_val_t[((size_t)b * NN + n0 + pt) * CC + c];
        }
        {   // gather key rows (contiguous 256B per neighbor in transposed layout)
            int pt = t >> 7, r = t & 127, c8 = r >> 4, k = r & 15;
            int j = s.idxs[pt][k];
            const float4* kp = (const float4*)&g_key_t[((size_t)b * NN + j) * CC + c8 * 8];
            float4 v0 = kp[0], v1 = kp[1];
            int cb = c8 * 8;
            s.kgu[pt][cb + 0][k] = v0.x; s.kgu[pt][cb + 1][k] = v0.y;
            s.kgu[pt][cb + 2][k] = v0.z; s.kgu[pt][cb + 3][k] = v0.w;
            s.kgu[pt][cb + 4][k] = v1.x; s.kgu[pt][cb + 5][k] = v1.y;
            s.kgu[pt][cb + 6][k] = v1.z; s.kgu[pt][cb + 7][k] = v1.w;
        }
        __syncthreads();

        // ---- stage 1: th = relu(bn(P1@pos_rel + pb1))  (folded) ----
        {
            int h = t & 63, kg = t >> 6;
#pragma unroll
            for (int pt = 0; pt < 2; pt++) {
                float4 o;
                float* ov = (float*)&o;
#pragma unroll
                for (int kk = 0; kk < 4; kk++) {
                    int k = kg * 4 + kk;
                    float a = s.pb1p[h]
                            + s.P1p[h][0] * s.posr[pt][0][k]
                            + s.P1p[h][1] * s.posr[pt][1][k]
                            + s.P1p[h][2] * s.posr[pt][2][k];
                    ov[kk] = fmaxf(a, 0.0f);
                }
                *(float4*)&s.th[pt][h][kg * 4] = o;
            }
        }
        __syncthreads();

        // ---- stage 2: pe = P2 @ th + pb2 ----
        {
            int c = t & 63, kg = t >> 6;
            float pb = s.pb2s[c];
            float4 a0 = make_float4(pb, pb, pb, pb);
            float4 a1 = a0;
#pragma unroll 4
            for (int h = 0; h < 64; h++) {
                float w = s.P2s[h][c];
                float4 t0 = *(const float4*)&s.th[0][h][kg * 4];
                float4 t1 = *(const float4*)&s.th[1][h][kg * 4];
                fma4(a0, w, t0);
                fma4(a1, w, t1);
            }
            *(float4*)&s.pes[0][c][kg * 4] = a0;
            *(float4*)&s.pes[1][c][kg * 4] = a1;
        }
        __syncthreads();

        // ---- stage 3: u = (query - key_g) + pe, in place over kgu ----
        {
            int c = t & 63, kg = t >> 6;
#pragma unroll
            for (int pt = 0; pt < 2; pt++) {
                float q = s.qy[pt][c];
                float4 kv = *(const float4*)&s.kgu[pt][c][kg * 4];
                float4 pv = *(const float4*)&s.pes[pt][c][kg * 4];
                float4 u;
                u.x = (q - kv.x) + pv.x;
                u.y = (q - kv.y) + pv.y;
                u.z = (q - kv.z) + pv.z;
                u.w = (q - kv.w) + pv.w;
                *(float4*)&s.kgu[pt][c][kg * 4] = u;
            }
        }
        __syncthreads();

        // ---- stage 4: h1 = relu(A1' @ u + b1')  (one row per thread, 32 accumulators) ----
        {
            int a = t;
            float bb = s.b1p[a];
            float4 ac[2][4];
#pragma unroll
            for (int pt = 0; pt < 2; pt++)
#pragma unroll
                for (int g = 0; g < 4; g++) ac[pt][g] = make_float4(bb, bb, bb, bb);
#pragma unroll 2
            for (int c = 0; c < 64; c++) {
                float w = s.A1s[c][a];
#pragma unroll
                for (int pt = 0; pt < 2; pt++) {
#pragma unroll
                    for (int g = 0; g < 4; g++) {
                        float4 u = *(const float4*)&s.kgu[pt][c][g * 4];
                        fma4(ac[pt][g], w, u);
                    }
                }
            }
#pragma unroll
            for (int pt = 0; pt < 2; pt++)
#pragma unroll
                for (int g = 0; g < 4; g++) {
                    float4 v = ac[pt][g];
                    v.x = fmaxf(v.x, 0.0f); v.y = fmaxf(v.y, 0.0f);
                    v.z = fmaxf(v.z, 0.0f); v.w = fmaxf(v.w, 0.0f);
                    *(float4*)&s.h1s[pt][a][g * 4] = v;
                }
        }
        __syncthreads();

        // ---- stage 5: attn logits = A2 @ h1 + ab2 (into th) ----
        {
            int c = t & 63, kg = t >> 6;
            float ab = s.ab2s[c];
            float4 a0 = make_float4(ab, ab, ab, ab);
            float4 a1 = a0;
#pragma unroll 4
            for (int h = 0; h < 256; h++) {
                float w = s.A2s[h][c];
                float4 h0 = *(const float4*)&s.h1s[0][h][kg * 4];
                float4 h1v = *(const float4*)&s.h1s[1][h][kg * 4];
                fma4(a0, w, h0);
                fma4(a1, w, h1v);
            }
            *(float4*)&s.th[0][c][kg * 4] = a0;
            *(float4*)&s.th[1][c][kg * 4] = a1;
        }
        __syncthreads();

        // ---- stage 6: softmax over k + aggregate + write ----
        if (t < 128) {
            int pt = t >> 6, c = t & 63;
            float av[16];
#pragma unroll
            for (int g = 0; g < 4; g++) {
                float4 v = *(const float4*)&s.th[pt][c][g * 4];
                av[g * 4 + 0] = v.x; av[g * 4 + 1] = v.y;
                av[g * 4 + 2] = v.z; av[g * 4 + 3] = v.w;
            }
            float m = av[0];
#pragma unroll
            for (int k = 1; k < 16; k++) m = fmaxf(m, av[k]);
            float vsum = 0.0f, acc = 0.0f;
            float vv = s.vals[pt][c];
#pragma unroll
            for (int k = 0; k < 16; k++) {
                float e = __expf(av[k] - m);
                vsum += e;
                acc = fmaf(e, vv + s.pes[pt][c][k], acc);
            }
            g_agg[((size_t)b * NN + n0 + pt) * CC + c] = acc / vsum;
        }
        __syncthreads();
    }
}

// ================= Kernel 4: out = W_end @ agg + b_end + y =================
__global__ __launch_bounds__(256) void k_end(
    const float* __restrict__ y, const float* __restrict__ We_g,
    const float* __restrict__ be_g, float* __restrict__ out)
{
    __shared__ float As[64][65];
    __shared__ float Ws[64][64];
    int b = blockIdx.y, n0 = blockIdx.x * 64, t = threadIdx.x;
#pragma unroll
    for (int i = 0; i < 16; i++) { int e = t + i * 256; Ws[e >> 6][e & 63] = We_g[e]; }
#pragma unroll
    for (int i = 0; i < 16; i++) {
        int e = t + i * 256; int p = e >> 6, c = e & 63;
        As[p][c] = g_agg[((size_t)b * NN + n0 + p) * CC + c];
    }
    __syncthreads();
    int p = t & 63, og = t >> 6;
    float acc[16];
#pragma unroll
    for (int i = 0; i < 16; i++) acc[i] = be_g[og * 16 + i];
#pragma unroll 4
    for (int c = 0; c < 64; c++) {
        float av = As[p][c];
#pragma unroll
        for (int i = 0; i < 16; i++) acc[i] = fmaf(Ws[og * 16 + i][c], av, acc[i]);
    }
#pragma unroll
    for (int i = 0; i < 16; i++) {
        int o = og * 16 + i;
        size_t off = ((size_t)b * CC + o) * NN + n0 + p;
        out[off] = acc[i] + y[off];
    }
}

// ================= launcher =================
extern "C" void kernel_launch(void* const* d_in, const int* in_sizes, int n_in,
                              void* d_out, int out_size)
{
    const float* x       = (const float*)d_in[0];
    const float* y       = (const float*)d_in[1];
    const float* W_start = (const float*)d_in[2];
    const float* b_start = (const float*)d_in[3];
    const float* W_key   = (const float*)d_in[4];
    const float* b_key   = (const float*)d_in[5];
    const float* W_query = (const float*)d_in[6];
    const float* b_query = (const float*)d_in[7];
    const float* P1      = (const float*)d_in[8];
    const float* pb1     = (const float*)d_in[9];
    const float* bn1_g   = (const float*)d_in[10];
    const float* bn1_b   = (const float*)d_in[11];
    const float* bn1_m   = (const float*)d_in[12];
    const float* bn1_v   = (const float*)d_in[13];
    const float* P2      = (const float*)d_in[14];
    const float* pb2     = (const float*)d_in[15];
    const float* A1      = (const float*)d_in[16];
    const float* ab1     = (const float*)d_in[17];
    const float* bn2_g   = (const float*)d_in[18];
    const float* bn2_b   = (const float*)d_in[19];
    const float* bn2_m   = (const float*)d_in[20];
    const float* bn2_v   = (const float*)d_in[21];
    const float* A2      = (const float*)d_in[22];
    const float* ab2     = (const float*)d_in[23];
    const float* W_end   = (const float*)d_in[24];
    const float* b_end   = (const float*)d_in[25];
    // d_in[26] = n_knn (compile-time 16)

    // opt-in to large dynamic smem (idempotent; harmless no-op if it errors during capture
    // since the attribute persists from the correctness call)
    cudaFuncSetAttribute(k_attn, cudaFuncAttributeMaxDynamicSharedMemorySize, (int)sizeof(S3));

    k_linear_start_key<<<dim3(NN / 64, BB), 256>>>(y, W_start, b_start, W_key, b_key);
    k_knn<<<dim3(NN / 128, BB), 128>>>(x);
    k_attn<<<BB * NN / 8, 256, sizeof(S3)>>>(x, W_query, b_query,
                                             P1, pb1, bn1_g, bn1_b, bn1_m, bn1_v,
                                             P2, pb2, A1, ab1,
                                             bn2_g, bn2_b, bn2_m, bn2_v, A2, ab2);
    k_end<<<dim3(NN / 64, BB), 256>>>(y, W_end, b_end, (float*)d_out);
}